// round 2
// baseline (speedup 1.0000x reference)
#include <cuda_runtime.h>
#include <math_constants.h>

// Problem constants
#define Bv 4
#define Sv 2048
#define Dv 1024
#define Hv 16
#define HDv 64
#define N3v 3072
#define Mv (Bv*Sv)   // 8192

// ---------------- scratch (device globals; no runtime allocation) -------------
__device__ __align__(256) float g_q[Bv*Hv*Sv*HDv];   // (b,h,s,hd), pre-scaled
__device__ __align__(256) float g_k[Bv*Hv*Sv*HDv];
__device__ __align__(256) float g_v[Bv*Hv*Sv*HDv];
__device__ __align__(256) float g_ctx[Mv*Dv];        // attention output (b,s,d)

// =============================================================================
// Kernel 1: QKV projection  C = X(8192x1024) @ W(1024x3072) + b
// 128x128 tile, BK=8, 256 threads, 8x8 register microtile.
// Epilogue scatters into g_q/g_k/g_v with (b,h,s,hd) layout; q gets *0.125.
// =============================================================================
__global__ __launch_bounds__(256) void gemm_qkv_kernel(
    const float* __restrict__ X,
    const float* __restrict__ W,
    const float* __restrict__ bias)
{
    __shared__ float As[8][128];
    __shared__ float Bs[8][128];

    const int t  = threadIdx.x;
    const int bx = blockIdx.x;   // N tile (24)
    const int by = blockIdx.y;   // M tile (64)
    const int tx = t & 15, ty = t >> 4;
    const int row0 = by * 128;
    const int col0 = bx * 128;

    const int aRow = t >> 1;           // 0..127
    const int aCol = (t & 1) * 4;      // 0 or 4
    const int bRow = t >> 5;           // 0..7
    const int bCol = (t & 31) * 4;     // 0..124

    float acc[8][8];
    #pragma unroll
    for (int i = 0; i < 8; i++)
        #pragma unroll
        for (int j = 0; j < 8; j++) acc[i][j] = 0.f;

    for (int k0 = 0; k0 < Dv; k0 += 8) {
        float4 a = *reinterpret_cast<const float4*>(&X[(row0 + aRow) * Dv + k0 + aCol]);
        As[aCol + 0][aRow] = a.x;
        As[aCol + 1][aRow] = a.y;
        As[aCol + 2][aRow] = a.z;
        As[aCol + 3][aRow] = a.w;
        float4 bv = *reinterpret_cast<const float4*>(&W[(k0 + bRow) * N3v + col0 + bCol]);
        *reinterpret_cast<float4*>(&Bs[bRow][bCol]) = bv;
        __syncthreads();
        #pragma unroll
        for (int kk = 0; kk < 8; kk++) {
            float ar[8], br[8];
            *(float4*)&ar[0] = *(float4*)&As[kk][ty * 8];
            *(float4*)&ar[4] = *(float4*)&As[kk][ty * 8 + 4];
            *(float4*)&br[0] = *(float4*)&Bs[kk][tx * 8];
            *(float4*)&br[4] = *(float4*)&Bs[kk][tx * 8 + 4];
            #pragma unroll
            for (int i = 0; i < 8; i++)
                #pragma unroll
                for (int j = 0; j < 8; j++)
                    acc[i][j] += ar[i] * br[j];
        }
        __syncthreads();
    }

    // Epilogue: scatter into q/k/v
    #pragma unroll
    for (int i = 0; i < 8; i++) {
        const int m = row0 + ty * 8 + i;
        const int bb = m >> 11;          // /2048
        const int s  = m & 2047;
        #pragma unroll
        for (int j = 0; j < 8; j++) {
            const int n = col0 + tx * 8 + j;
            float v = acc[i][j] + bias[n];
            const int sel = n >> 10;     // 0=q 1=k 2=v
            const int d   = n & 1023;
            const int h   = d >> 6;
            const int hd  = d & 63;
            const int idx = ((bb * Hv + h) * Sv + s) * HDv + hd;
            if (sel == 0)      g_q[idx] = v * 0.125f;
            else if (sel == 1) g_k[idx] = v;
            else               g_v[idx] = v;
        }
    }
}

// =============================================================================
// Kernel 2: fp32 flash attention. One block = (b, h, 64 q-rows).
// 256 threads; microtile 4x4 with interleaved mapping row=ty+16i, col=tx+16j.
// smem tiles pitch 65 (conflict-free), online softmax, masked keys -> -1e30.
// =============================================================================
#define PT 65
#define ATTN_SMEM_BYTES ((4 * 64 * PT + 64 * 3 + 256) * 4 + 64 * 4)

__global__ __launch_bounds__(256) void attn_kernel(const int* __restrict__ mask)
{
    extern __shared__ float sm[];
    float* sQ   = sm;                 // [hd][r]  pitch PT
    float* sK   = sQ + 64 * PT;       // [hd][c]  pitch PT
    float* sV   = sK + 64 * PT;       // [c][hd]  pitch PT
    float* sS   = sV + 64 * PT;       // [r][c]   pitch PT
    float* m_s    = sS + 64 * PT;     // 64
    float* l_s    = m_s + 64;         // 64
    float* corr_s = l_s + 64;         // 64
    float* red    = corr_s + 64;      // 256
    int*   smask  = (int*)(red + 256);// 64

    const int t  = threadIdx.x;
    const int qt = blockIdx.x;
    const int h  = blockIdx.y;
    const int b  = blockIdx.z;
    const int tx = t & 15, ty = t >> 4;

    const int rr = t >> 2;            // 0..63 (row for tile loads)
    const int qd = (t & 3) * 16;      // hd chunk start

    // ---- load Q tile transposed: sQ[hd][r] ----
    const float* qptr = g_q + ((b * Hv + h) * Sv + qt * 64) * HDv;
    #pragma unroll
    for (int u = 0; u < 4; u++) {
        float4 v = *(const float4*)&qptr[rr * 64 + qd + u * 4];
        sQ[(qd + u * 4 + 0) * PT + rr] = v.x;
        sQ[(qd + u * 4 + 1) * PT + rr] = v.y;
        sQ[(qd + u * 4 + 2) * PT + rr] = v.z;
        sQ[(qd + u * 4 + 3) * PT + rr] = v.w;
    }
    if (t < 64) { m_s[t] = -1e30f; l_s[t] = 0.f; }

    float o[4][4];
    #pragma unroll
    for (int i = 0; i < 4; i++)
        #pragma unroll
        for (int j = 0; j < 4; j++) o[i][j] = 0.f;

    const int r = t & 63;
    const int p = t >> 6;

    for (int kt = 0; kt < Sv / 64; kt++) {
        __syncthreads();   // protect prior-iteration smem reads

        // ---- load K (transposed) and V tiles ----
        const float* kptr = g_k + ((b * Hv + h) * Sv + kt * 64) * HDv;
        const float* vptr = g_v + ((b * Hv + h) * Sv + kt * 64) * HDv;
        #pragma unroll
        for (int u = 0; u < 4; u++) {
            float4 v = *(const float4*)&kptr[rr * 64 + qd + u * 4];
            sK[(qd + u * 4 + 0) * PT + rr] = v.x;
            sK[(qd + u * 4 + 1) * PT + rr] = v.y;
            sK[(qd + u * 4 + 2) * PT + rr] = v.z;
            sK[(qd + u * 4 + 3) * PT + rr] = v.w;
        }
        #pragma unroll
        for (int u = 0; u < 4; u++) {
            float4 v = *(const float4*)&vptr[rr * 64 + qd + u * 4];
            sV[rr * PT + qd + u * 4 + 0] = v.x;
            sV[rr * PT + qd + u * 4 + 1] = v.y;
            sV[rr * PT + qd + u * 4 + 2] = v.z;
            sV[rr * PT + qd + u * 4 + 3] = v.w;
        }
        if (t < 64) smask[t] = mask[b * Sv + kt * 64 + t];
        __syncthreads();

        // ---- scores: S = Q K^T (q pre-scaled) ----
        float sc[4][4];
        #pragma unroll
        for (int i = 0; i < 4; i++)
            #pragma unroll
            for (int j = 0; j < 4; j++) sc[i][j] = 0.f;
        #pragma unroll 4
        for (int k = 0; k < 64; k++) {
            float a[4], bb2[4];
            #pragma unroll
            for (int i = 0; i < 4; i++) a[i]   = sQ[k * PT + ty + 16 * i];
            #pragma unroll
            for (int j = 0; j < 4; j++) bb2[j] = sK[k * PT + tx + 16 * j];
            #pragma unroll
            for (int i = 0; i < 4; i++)
                #pragma unroll
                for (int j = 0; j < 4; j++)
                    sc[i][j] += a[i] * bb2[j];
        }
        #pragma unroll
        for (int i = 0; i < 4; i++)
            #pragma unroll
            for (int j = 0; j < 4; j++) {
                const int c = tx + 16 * j;
                sS[(ty + 16 * i) * PT + c] = smask[c] ? sc[i][j] : -1e30f;
            }
        __syncthreads();

        // ---- row max (4 partials per row) ----
        {
            float mx = -1e30f;
            const int c0 = p * 16;
            #pragma unroll
            for (int c = 0; c < 16; c++) mx = fmaxf(mx, sS[r * PT + c0 + c]);
            red[p * 64 + r] = mx;
        }
        __syncthreads();
        if (t < 64) {
            float mt = fmaxf(fmaxf(red[t], red[64 + t]), fmaxf(red[128 + t], red[192 + t]));
            float m_old = m_s[t];
            float m_new = fmaxf(m_old, mt);
            float corr  = __expf(m_old - m_new);
            m_s[t] = m_new; corr_s[t] = corr; l_s[t] *= corr;
        }
        __syncthreads();

        // ---- exponentiate + partial row sums ----
        {
            const float mrow = m_s[r];
            float lsum = 0.f;
            const int c0 = p * 16;
            #pragma unroll
            for (int c = 0; c < 16; c++) {
                float e = __expf(sS[r * PT + c0 + c] - mrow);
                sS[r * PT + c0 + c] = e;
                lsum += e;
            }
            red[p * 64 + r] = lsum;
        }
        __syncthreads();
        if (t < 64) l_s[t] += red[t] + red[64 + t] + red[128 + t] + red[192 + t];

        // ---- rescale accumulators, then O += P V ----
        #pragma unroll
        for (int i = 0; i < 4; i++) {
            const float cf = corr_s[ty + 16 * i];
            #pragma unroll
            for (int j = 0; j < 4; j++) o[i][j] *= cf;
        }
        #pragma unroll 4
        for (int c = 0; c < 64; c++) {
            float a[4], bb2[4];
            #pragma unroll
            for (int i = 0; i < 4; i++) a[i]   = sS[(ty + 16 * i) * PT + c];
            #pragma unroll
            for (int j = 0; j < 4; j++) bb2[j] = sV[c * PT + tx + 16 * j];
            #pragma unroll
            for (int i = 0; i < 4; i++)
                #pragma unroll
                for (int j = 0; j < 4; j++)
                    o[i][j] += a[i] * bb2[j];
        }
    }
    __syncthreads();

    // ---- normalize and write to (b,s,d) context ----
    float* optr = g_ctx + (size_t)(b * Sv + qt * 64) * Dv + h * HDv;
    #pragma unroll
    for (int i = 0; i < 4; i++) {
        const int rl = ty + 16 * i;
        const float inv = 1.0f / l_s[rl];
        #pragma unroll
        for (int j = 0; j < 4; j++)
            optr[rl * Dv + tx + 16 * j] = o[i][j] * inv;
    }
}

// =============================================================================
// Kernel 3: output projection  out = ctx(8192x1024) @ Wo(1024x1024) + b_out
// =============================================================================
__global__ __launch_bounds__(256) void gemm_out_kernel(
    const float* __restrict__ W,
    const float* __restrict__ bias,
    float* __restrict__ out)
{
    __shared__ float As[8][128];
    __shared__ float Bs[8][128];

    const int t  = threadIdx.x;
    const int bx = blockIdx.x;   // N tile (8)
    const int by = blockIdx.y;   // M tile (64)
    const int tx = t & 15, ty = t >> 4;
    const int row0 = by * 128;
    const int col0 = bx * 128;

    const int aRow = t >> 1;
    const int aCol = (t & 1) * 4;
    const int bRow = t >> 5;
    const int bCol = (t & 31) * 4;

    float acc[8][8];
    #pragma unroll
    for (int i = 0; i < 8; i++)
        #pragma unroll
        for (int j = 0; j < 8; j++) acc[i][j] = 0.f;

    for (int k0 = 0; k0 < Dv; k0 += 8) {
        float4 a = *reinterpret_cast<const float4*>(&g_ctx[(size_t)(row0 + aRow) * Dv + k0 + aCol]);
        As[aCol + 0][aRow] = a.x;
        As[aCol + 1][aRow] = a.y;
        As[aCol + 2][aRow] = a.z;
        As[aCol + 3][aRow] = a.w;
        float4 bv = *reinterpret_cast<const float4*>(&W[(k0 + bRow) * Dv + col0 + bCol]);
        *reinterpret_cast<float4*>(&Bs[bRow][bCol]) = bv;
        __syncthreads();
        #pragma unroll
        for (int kk = 0; kk < 8; kk++) {
            float ar[8], br[8];
            *(float4*)&ar[0] = *(float4*)&As[kk][ty * 8];
            *(float4*)&ar[4] = *(float4*)&As[kk][ty * 8 + 4];
            *(float4*)&br[0] = *(float4*)&Bs[kk][tx * 8];
            *(float4*)&br[4] = *(float4*)&Bs[kk][tx * 8 + 4];
            #pragma unroll
            for (int i = 0; i < 8; i++)
                #pragma unroll
                for (int j = 0; j < 8; j++)
                    acc[i][j] += ar[i] * br[j];
        }
        __syncthreads();
    }

    #pragma unroll
    for (int i = 0; i < 8; i++) {
        const int m = row0 + ty * 8 + i;
        #pragma unroll
        for (int jj = 0; jj < 2; jj++) {
            const int n = col0 + tx * 8 + jj * 4;
            float4 v;
            v.x = acc[i][jj * 4 + 0] + bias[n + 0];
            v.y = acc[i][jj * 4 + 1] + bias[n + 1];
            v.z = acc[i][jj * 4 + 2] + bias[n + 2];
            v.w = acc[i][jj * 4 + 3] + bias[n + 3];
            *reinterpret_cast<float4*>(&out[(size_t)m * Dv + n]) = v;
        }
    }
}

// =============================================================================
extern "C" void kernel_launch(void* const* d_in, const int* in_sizes, int n_in,
                              void* d_out, int out_size)
{
    const float* x     = (const float*)d_in[0];
    const float* w_in  = (const float*)d_in[1];
    const float* b_in  = (const float*)d_in[2];
    const float* w_out = (const float*)d_in[3];
    const float* b_out = (const float*)d_in[4];
    const int*   mask  = (const int*)d_in[5];
    float* out = (float*)d_out;

    cudaFuncSetAttribute(attn_kernel, cudaFuncAttributeMaxDynamicSharedMemorySize,
                         ATTN_SMEM_BYTES);

    gemm_qkv_kernel<<<dim3(N3v / 128, Mv / 128), 256>>>(x, w_in, b_in);
    attn_kernel<<<dim3(Sv / 64, Hv, Bv), 256, ATTN_SMEM_BYTES>>>(mask);
    gemm_out_kernel<<<dim3(Dv / 128, Mv / 128), 256>>>(w_out, b_out, out);
}

// round 3
// speedup vs baseline: 2.3865x; 2.3865x over previous
#include <cuda_runtime.h>

// Problem constants
#define Bv 4
#define Sv 2048
#define Dv 1024
#define Hv 16
#define HDv 64
#define N3v 3072
#define Mv (Bv*Sv)   // 8192

// ---------------- scratch (device globals; no runtime allocation) -------------
__device__ __align__(256) float g_q[Bv*Hv*Sv*HDv];   // (b,h,s,hd), q pre-scaled
__device__ __align__(256) float g_k[Bv*Hv*Sv*HDv];
__device__ __align__(256) float g_v[Bv*Hv*Sv*HDv];
__device__ __align__(256) float g_ctx[(size_t)Mv*Dv]; // attention output (b,s,d)

// ---------------- tf32 helpers ------------------------------------------------
__device__ __forceinline__ unsigned f2t(float f) {
    unsigned u;
    asm("cvt.rna.tf32.f32 %0, %1;" : "=r"(u) : "f"(f));
    return u;
}

__device__ __forceinline__ void mma8(float* c, const unsigned* a, const unsigned* b) {
    asm volatile(
        "mma.sync.aligned.m16n8k8.row.col.f32.tf32.tf32.f32 "
        "{%0,%1,%2,%3},{%4,%5,%6,%7},{%8,%9},{%0,%1,%2,%3};\n"
        : "+f"(c[0]), "+f"(c[1]), "+f"(c[2]), "+f"(c[3])
        : "r"(a[0]), "r"(a[1]), "r"(a[2]), "r"(a[3]),
          "r"(b[0]), "r"(b[1]));
}

// =============================================================================
// QKV scatter epilogue helper
// =============================================================================
__device__ __forceinline__ void qkv_store(int m, int n, float v, const float* __restrict__ bias) {
    v += bias[n];
    const int bb  = m >> 11;
    const int s   = m & 2047;
    const int sel = n >> 10;      // 0=q 1=k 2=v
    const int d   = n & 1023;
    const int h   = d >> 6;
    const int hd  = d & 63;
    const int idx = ((bb * Hv + h) * Sv + s) * HDv + hd;
    if (sel == 0)      g_q[idx] = v * 0.125f;
    else if (sel == 1) g_k[idx] = v;
    else               g_v[idx] = v;
}

// =============================================================================
// Kernel 1: QKV projection via tf32 mma.sync — C = X(8192x1024) @ W(1024x3072)+b
// 128x128 tile, BK=32, 256 threads (8 warps), warp tile 32x64.
// smem pitch 136: fragment loads bank = 8*t4 + g (+const) -> conflict-free.
// =============================================================================
#define GP 136

__global__ __launch_bounds__(256) void gemm_qkv_tc(
    const float* __restrict__ X,
    const float* __restrict__ W,
    const float* __restrict__ bias)
{
    __shared__ unsigned As[32 * GP];
    __shared__ unsigned Bs[32 * GP];

    const int t    = threadIdx.x;
    const int w    = t >> 5, lane = t & 31;
    const int g    = lane >> 2, tig = lane & 3;
    const int row0 = blockIdx.y * 128;
    const int col0 = blockIdx.x * 128;
    const int m0w  = (w & 3) * 32;
    const int n0w  = (w >> 2) * 64;

    const int ar  = t & 127;          // A row
    const int ah  = (t >> 7) * 16;    // A k-half
    const int bkr = t >> 3;           // B k-row
    const int bnc = (t & 7) * 16;     // B n-chunk

    float c[2][8][4];
    #pragma unroll
    for (int mt = 0; mt < 2; mt++)
        #pragma unroll
        for (int nt = 0; nt < 8; nt++)
            #pragma unroll
            for (int j = 0; j < 4; j++) c[mt][nt][j] = 0.f;

    for (int k0 = 0; k0 < Dv; k0 += 32) {
        // A tile -> As[k][m] (transposed, tf32)
        #pragma unroll
        for (int j = 0; j < 4; j++) {
            float4 v = *(const float4*)(X + (size_t)(row0 + ar) * Dv + k0 + ah + 4 * j);
            const int kb = ah + 4 * j;
            As[(kb + 0) * GP + ar] = f2t(v.x);
            As[(kb + 1) * GP + ar] = f2t(v.y);
            As[(kb + 2) * GP + ar] = f2t(v.z);
            As[(kb + 3) * GP + ar] = f2t(v.w);
        }
        // B tile -> Bs[k][n] (tf32)
        #pragma unroll
        for (int j = 0; j < 4; j++) {
            float4 v = *(const float4*)(W + (size_t)(k0 + bkr) * N3v + col0 + bnc + 4 * j);
            uint4 u = make_uint4(f2t(v.x), f2t(v.y), f2t(v.z), f2t(v.w));
            *(uint4*)(Bs + bkr * GP + bnc + 4 * j) = u;
        }
        __syncthreads();

        #pragma unroll
        for (int ks = 0; ks < 4; ks++) {
            const int kk = ks * 8;
            unsigned a[2][4], b[8][2];
            #pragma unroll
            for (int mt = 0; mt < 2; mt++) {
                const int mb = m0w + mt * 16;
                a[mt][0] = As[(kk + tig) * GP + mb + g];
                a[mt][1] = As[(kk + tig) * GP + mb + g + 8];
                a[mt][2] = As[(kk + tig + 4) * GP + mb + g];
                a[mt][3] = As[(kk + tig + 4) * GP + mb + g + 8];
            }
            #pragma unroll
            for (int nt = 0; nt < 8; nt++) {
                b[nt][0] = Bs[(kk + tig) * GP + n0w + nt * 8 + g];
                b[nt][1] = Bs[(kk + tig + 4) * GP + n0w + nt * 8 + g];
            }
            #pragma unroll
            for (int mt = 0; mt < 2; mt++)
                #pragma unroll
                for (int nt = 0; nt < 8; nt++)
                    mma8(c[mt][nt], a[mt], b[nt]);
        }
        __syncthreads();
    }

    // epilogue: scatter to q/k/v
    #pragma unroll
    for (int mt = 0; mt < 2; mt++) {
        const int r0 = row0 + m0w + mt * 16 + g;
        const int r1 = r0 + 8;
        #pragma unroll
        for (int nt = 0; nt < 8; nt++) {
            const int n = col0 + n0w + nt * 8 + 2 * tig;
            qkv_store(r0, n,     c[mt][nt][0], bias);
            qkv_store(r0, n + 1, c[mt][nt][1], bias);
            qkv_store(r1, n,     c[mt][nt][2], bias);
            qkv_store(r1, n + 1, c[mt][nt][3], bias);
        }
    }
}

// =============================================================================
// Kernel 3: out projection via tf32 mma.sync — out = ctx @ Wo(1024x1024) + b
// =============================================================================
__global__ __launch_bounds__(256) void gemm_out_tc(
    const float* __restrict__ W,
    const float* __restrict__ bias,
    float* __restrict__ out)
{
    __shared__ unsigned As[32 * GP];
    __shared__ unsigned Bs[32 * GP];

    const int t    = threadIdx.x;
    const int w    = t >> 5, lane = t & 31;
    const int g    = lane >> 2, tig = lane & 3;
    const int row0 = blockIdx.y * 128;
    const int col0 = blockIdx.x * 128;
    const int m0w  = (w & 3) * 32;
    const int n0w  = (w >> 2) * 64;

    const int ar  = t & 127;
    const int ah  = (t >> 7) * 16;
    const int bkr = t >> 3;
    const int bnc = (t & 7) * 16;

    float c[2][8][4];
    #pragma unroll
    for (int mt = 0; mt < 2; mt++)
        #pragma unroll
        for (int nt = 0; nt < 8; nt++)
            #pragma unroll
            for (int j = 0; j < 4; j++) c[mt][nt][j] = 0.f;

    for (int k0 = 0; k0 < Dv; k0 += 32) {
        #pragma unroll
        for (int j = 0; j < 4; j++) {
            float4 v = *(const float4*)(g_ctx + (size_t)(row0 + ar) * Dv + k0 + ah + 4 * j);
            const int kb = ah + 4 * j;
            As[(kb + 0) * GP + ar] = f2t(v.x);
            As[(kb + 1) * GP + ar] = f2t(v.y);
            As[(kb + 2) * GP + ar] = f2t(v.z);
            As[(kb + 3) * GP + ar] = f2t(v.w);
        }
        #pragma unroll
        for (int j = 0; j < 4; j++) {
            float4 v = *(const float4*)(W + (size_t)(k0 + bkr) * Dv + col0 + bnc + 4 * j);
            uint4 u = make_uint4(f2t(v.x), f2t(v.y), f2t(v.z), f2t(v.w));
            *(uint4*)(Bs + bkr * GP + bnc + 4 * j) = u;
        }
        __syncthreads();

        #pragma unroll
        for (int ks = 0; ks < 4; ks++) {
            const int kk = ks * 8;
            unsigned a[2][4], b[8][2];
            #pragma unroll
            for (int mt = 0; mt < 2; mt++) {
                const int mb = m0w + mt * 16;
                a[mt][0] = As[(kk + tig) * GP + mb + g];
                a[mt][1] = As[(kk + tig) * GP + mb + g + 8];
                a[mt][2] = As[(kk + tig + 4) * GP + mb + g];
                a[mt][3] = As[(kk + tig + 4) * GP + mb + g + 8];
            }
            #pragma unroll
            for (int nt = 0; nt < 8; nt++) {
                b[nt][0] = Bs[(kk + tig) * GP + n0w + nt * 8 + g];
                b[nt][1] = Bs[(kk + tig + 4) * GP + n0w + nt * 8 + g];
            }
            #pragma unroll
            for (int mt = 0; mt < 2; mt++)
                #pragma unroll
                for (int nt = 0; nt < 8; nt++)
                    mma8(c[mt][nt], a[mt], b[nt]);
        }
        __syncthreads();
    }

    #pragma unroll
    for (int mt = 0; mt < 2; mt++) {
        const int r0 = row0 + m0w + mt * 16 + g;
        const int r1 = r0 + 8;
        #pragma unroll
        for (int nt = 0; nt < 8; nt++) {
            const int n = col0 + n0w + nt * 8 + 2 * tig;
            float2 v0 = make_float2(c[mt][nt][0] + bias[n], c[mt][nt][1] + bias[n + 1]);
            float2 v1 = make_float2(c[mt][nt][2] + bias[n], c[mt][nt][3] + bias[n + 1]);
            *(float2*)(out + (size_t)r0 * Dv + n) = v0;
            *(float2*)(out + (size_t)r1 * Dv + n) = v1;
        }
    }
}

// =============================================================================
// Kernel 2: tf32 tensor-core flash attention.
// Block = 128 threads (4 warps); each warp owns 16 q-rows x ALL 64 keys,
// so softmax is entirely register+shuffle resident. P (C-frag) -> A-frag via
// intra-quad shuffles. sK pitch 68 / sV pitch 72: conflict-free B-frag loads.
// =============================================================================
#define PK 68
#define PV 72

__global__ __launch_bounds__(128) void attn_tc(const int* __restrict__ mask)
{
    __shared__ unsigned sK[64 * PK];
    __shared__ unsigned sV[64 * PV];
    __shared__ int smask[64];

    const int t    = threadIdx.x;
    const int w    = t >> 5, lane = t & 31;
    const int g    = lane >> 2, tig = lane & 3;
    const int qt   = blockIdx.x;
    const int h    = blockIdx.y;
    const int b    = blockIdx.z;
    const size_t bh = ((size_t)b * Hv + h) * Sv;

    // ---- preload Q fragments (rows w*16 .. w*16+15), tf32 ----
    unsigned q[8][4];
    const float* qp = g_q + (bh + qt * 64 + w * 16) * HDv;
    #pragma unroll
    for (int ks = 0; ks < 8; ks++) {
        q[ks][0] = f2t(qp[g * 64       + ks * 8 + tig]);
        q[ks][1] = f2t(qp[(g + 8) * 64 + ks * 8 + tig]);
        q[ks][2] = f2t(qp[g * 64       + ks * 8 + tig + 4]);
        q[ks][3] = f2t(qp[(g + 8) * 64 + ks * 8 + tig + 4]);
    }

    float o[8][4];
    #pragma unroll
    for (int nt = 0; nt < 8; nt++)
        #pragma unroll
        for (int j = 0; j < 4; j++) o[nt][j] = 0.f;

    float m0r = -1e30f, m1r = -1e30f, l0 = 0.f, l1 = 0.f;

    const int lr = t >> 1;            // 0..63 tile-load row
    const int lh = (t & 1) * 32;      // col half
    const int sub = tig & 1;
    const int sl0 = (lane & ~3) | (tig >> 1);
    const int sl2 = sl0 + 2;

    for (int kt = 0; kt < Sv / 64; kt++) {
        __syncthreads();   // protect prior-iteration smem reads

        // ---- load K/V tiles as tf32 ----
        const float* kp = g_k + (bh + kt * 64) * HDv;
        const float* vp = g_v + (bh + kt * 64) * HDv;
        #pragma unroll
        for (int j = 0; j < 8; j++) {
            float4 kv = *(const float4*)(kp + lr * 64 + lh + 4 * j);
            *(uint4*)(sK + lr * PK + lh + 4 * j) =
                make_uint4(f2t(kv.x), f2t(kv.y), f2t(kv.z), f2t(kv.w));
            float4 vv = *(const float4*)(vp + lr * 64 + lh + 4 * j);
            *(uint4*)(sV + lr * PV + lh + 4 * j) =
                make_uint4(f2t(vv.x), f2t(vv.y), f2t(vv.z), f2t(vv.w));
        }
        if (t < 64) smask[t] = mask[b * Sv + kt * 64 + t];
        __syncthreads();

        // ---- S = Q K^T ----
        float s[8][4];
        #pragma unroll
        for (int nt = 0; nt < 8; nt++)
            #pragma unroll
            for (int j = 0; j < 4; j++) s[nt][j] = 0.f;

        #pragma unroll
        for (int ks = 0; ks < 8; ks++) {
            const int kk = ks * 8;
            #pragma unroll
            for (int nt = 0; nt < 8; nt++) {
                unsigned bb[2];
                bb[0] = sK[(nt * 8 + g) * PK + kk + tig];
                bb[1] = sK[(nt * 8 + g) * PK + kk + tig + 4];
                mma8(s[nt], q[ks], bb);
            }
        }

        // ---- mask ----
        #pragma unroll
        for (int nt = 0; nt < 8; nt++) {
            const int cc = nt * 8 + 2 * tig;
            if (!smask[cc])     { s[nt][0] = -1e30f; s[nt][2] = -1e30f; }
            if (!smask[cc + 1]) { s[nt][1] = -1e30f; s[nt][3] = -1e30f; }
        }

        // ---- row max (regs + quad shuffle) ----
        float mx0 = -1e30f, mx1 = -1e30f;
        #pragma unroll
        for (int nt = 0; nt < 8; nt++) {
            mx0 = fmaxf(mx0, fmaxf(s[nt][0], s[nt][1]));
            mx1 = fmaxf(mx1, fmaxf(s[nt][2], s[nt][3]));
        }
        mx0 = fmaxf(mx0, __shfl_xor_sync(0xffffffffu, mx0, 1));
        mx0 = fmaxf(mx0, __shfl_xor_sync(0xffffffffu, mx0, 2));
        mx1 = fmaxf(mx1, __shfl_xor_sync(0xffffffffu, mx1, 1));
        mx1 = fmaxf(mx1, __shfl_xor_sync(0xffffffffu, mx1, 2));

        const float mn0 = fmaxf(m0r, mx0);
        const float mn1 = fmaxf(m1r, mx1);
        const float cr0 = __expf(m0r - mn0);
        const float cr1 = __expf(m1r - mn1);
        m0r = mn0; m1r = mn1;

        // ---- exp + row sums ----
        float a0 = 0.f, a1 = 0.f;
        #pragma unroll
        for (int nt = 0; nt < 8; nt++) {
            s[nt][0] = __expf(s[nt][0] - mn0);
            s[nt][1] = __expf(s[nt][1] - mn0);
            s[nt][2] = __expf(s[nt][2] - mn1);
            s[nt][3] = __expf(s[nt][3] - mn1);
            a0 += s[nt][0] + s[nt][1];
            a1 += s[nt][2] + s[nt][3];
        }
        a0 += __shfl_xor_sync(0xffffffffu, a0, 1);
        a0 += __shfl_xor_sync(0xffffffffu, a0, 2);
        a1 += __shfl_xor_sync(0xffffffffu, a1, 1);
        a1 += __shfl_xor_sync(0xffffffffu, a1, 2);
        l0 = l0 * cr0 + a0;
        l1 = l1 * cr1 + a1;

        // ---- rescale O ----
        #pragma unroll
        for (int nt = 0; nt < 8; nt++) {
            o[nt][0] *= cr0; o[nt][1] *= cr0;
            o[nt][2] *= cr1; o[nt][3] *= cr1;
        }

        // ---- P -> tf32 (in place) ----
        #pragma unroll
        for (int nt = 0; nt < 8; nt++)
            #pragma unroll
            for (int j = 0; j < 4; j++)
                s[nt][j] = __uint_as_float(f2t(s[nt][j]));

        // ---- O += P V  (C-frag -> A-frag via quad shuffles) ----
        #pragma unroll
        for (int ks = 0; ks < 8; ks++) {
            unsigned a[4];
            float p0 = __shfl_sync(0xffffffffu, s[ks][0], sl0);
            float p1 = __shfl_sync(0xffffffffu, s[ks][1], sl0);
            a[0] = __float_as_uint(sub ? p1 : p0);
            float p2 = __shfl_sync(0xffffffffu, s[ks][2], sl0);
            float p3 = __shfl_sync(0xffffffffu, s[ks][3], sl0);
            a[1] = __float_as_uint(sub ? p3 : p2);
            float r0 = __shfl_sync(0xffffffffu, s[ks][0], sl2);
            float r1 = __shfl_sync(0xffffffffu, s[ks][1], sl2);
            a[2] = __float_as_uint(sub ? r1 : r0);
            float r2 = __shfl_sync(0xffffffffu, s[ks][2], sl2);
            float r3 = __shfl_sync(0xffffffffu, s[ks][3], sl2);
            a[3] = __float_as_uint(sub ? r3 : r2);

            const int kk = ks * 8;
            #pragma unroll
            for (int nt = 0; nt < 8; nt++) {
                unsigned bb[2];
                bb[0] = sV[(kk + tig) * PV + nt * 8 + g];
                bb[1] = sV[(kk + tig + 4) * PV + nt * 8 + g];
                mma8(o[nt], a, bb);
            }
        }
    }

    // ---- normalize and write context (b, s, d) ----
    const float inv0 = 1.0f / l0;
    const float inv1 = 1.0f / l1;
    float* op = g_ctx + (size_t)(b * Sv + qt * 64 + w * 16) * Dv + h * HDv;
    #pragma unroll
    for (int nt = 0; nt < 8; nt++) {
        const int cc = nt * 8 + 2 * tig;
        *(float2*)(op + (size_t)g * Dv + cc) =
            make_float2(o[nt][0] * inv0, o[nt][1] * inv0);
        *(float2*)(op + (size_t)(g + 8) * Dv + cc) =
            make_float2(o[nt][2] * inv1, o[nt][3] * inv1);
    }
}

// =============================================================================
extern "C" void kernel_launch(void* const* d_in, const int* in_sizes, int n_in,
                              void* d_out, int out_size)
{
    const float* x     = (const float*)d_in[0];
    const float* w_in  = (const float*)d_in[1];
    const float* b_in  = (const float*)d_in[2];
    const float* w_out = (const float*)d_in[3];
    const float* b_out = (const float*)d_in[4];
    const int*   mask  = (const int*)d_in[5];
    float* out = (float*)d_out;

    gemm_qkv_tc<<<dim3(N3v / 128, Mv / 128), 256>>>(x, w_in, b_in);
    attn_tc<<<dim3(Sv / 64, Hv, Bv), 128>>>(mask);
    gemm_out_tc<<<dim3(Dv / 128, Mv / 128), 256>>>(w_out, b_out, out);
}

// round 4
// speedup vs baseline: 2.3879x; 1.0006x over previous
#include <cuda_runtime.h>

// Problem constants
#define Bv 4
#define Sv 2048
#define Dv 1024
#define Hv 16
#define HDv 64
#define N3v 3072
#define Mv (Bv*Sv)   // 8192

// ---------------- scratch (device globals; no runtime allocation) -------------
__device__ __align__(256) float g_q[Bv*Hv*Sv*HDv];   // (b,h,s,hd), q pre-scaled
__device__ __align__(256) float g_k[Bv*Hv*Sv*HDv];
__device__ __align__(256) float g_v[Bv*Hv*Sv*HDv];
__device__ __align__(256) float g_ctx[(size_t)Mv*Dv]; // attention output (b,s,d)

// ---------------- tf32 helpers ------------------------------------------------
__device__ __forceinline__ unsigned f2t(float f) {
    unsigned u;
    asm("cvt.rna.tf32.f32 %0, %1;" : "=r"(u) : "f"(f));
    return u;
}

__device__ __forceinline__ void mma8(float* c, const unsigned* a, const unsigned* b) {
    asm volatile(
        "mma.sync.aligned.m16n8k8.row.col.f32.tf32.tf32.f32 "
        "{%0,%1,%2,%3},{%4,%5,%6,%7},{%8,%9},{%0,%1,%2,%3};\n"
        : "+f"(c[0]), "+f"(c[1]), "+f"(c[2]), "+f"(c[3])
        : "r"(a[0]), "r"(a[1]), "r"(a[2]), "r"(a[3]),
          "r"(b[0]), "r"(b[1]));
}

// =============================================================================
// QKV scatter epilogue helper
// =============================================================================
__device__ __forceinline__ void qkv_store(int m, int n, float v, const float* __restrict__ bias) {
    v += bias[n];
    const int bb  = m >> 11;
    const int s   = m & 2047;
    const int sel = n >> 10;      // 0=q 1=k 2=v
    const int d   = n & 1023;
    const int h   = d >> 6;
    const int hd  = d & 63;
    const int idx = ((bb * Hv + h) * Sv + s) * HDv + hd;
    if (sel == 0)      g_q[idx] = v * 0.125f;
    else if (sel == 1) g_k[idx] = v;
    else               g_v[idx] = v;
}

// =============================================================================
// Kernel 1: QKV projection via tf32 mma.sync — C = X(8192x1024) @ W(1024x3072)+b
// 128x128 tile, BK=32, 256 threads (8 warps), warp tile 32x64.
// smem pitch 136: fragment loads bank = 8*t4 + g (+const) -> conflict-free.
// =============================================================================
#define GP 136

__global__ __launch_bounds__(256) void gemm_qkv_tc(
    const float* __restrict__ X,
    const float* __restrict__ W,
    const float* __restrict__ bias)
{
    __shared__ unsigned As[32 * GP];
    __shared__ unsigned Bs[32 * GP];

    const int t    = threadIdx.x;
    const int w    = t >> 5, lane = t & 31;
    const int g    = lane >> 2, tig = lane & 3;
    const int row0 = blockIdx.y * 128;
    const int col0 = blockIdx.x * 128;
    const int m0w  = (w & 3) * 32;
    const int n0w  = (w >> 2) * 64;

    const int ar  = t & 127;          // A row
    const int ah  = (t >> 7) * 16;    // A k-half
    const int bkr = t >> 3;           // B k-row
    const int bnc = (t & 7) * 16;     // B n-chunk

    float c[2][8][4];
    #pragma unroll
    for (int mt = 0; mt < 2; mt++)
        #pragma unroll
        for (int nt = 0; nt < 8; nt++)
            #pragma unroll
            for (int j = 0; j < 4; j++) c[mt][nt][j] = 0.f;

    for (int k0 = 0; k0 < Dv; k0 += 32) {
        // A tile -> As[k][m] (transposed, tf32)
        #pragma unroll
        for (int j = 0; j < 4; j++) {
            float4 v = *(const float4*)(X + (size_t)(row0 + ar) * Dv + k0 + ah + 4 * j);
            const int kb = ah + 4 * j;
            As[(kb + 0) * GP + ar] = f2t(v.x);
            As[(kb + 1) * GP + ar] = f2t(v.y);
            As[(kb + 2) * GP + ar] = f2t(v.z);
            As[(kb + 3) * GP + ar] = f2t(v.w);
        }
        // B tile -> Bs[k][n] (tf32)
        #pragma unroll
        for (int j = 0; j < 4; j++) {
            float4 v = *(const float4*)(W + (size_t)(k0 + bkr) * N3v + col0 + bnc + 4 * j);
            uint4 u = make_uint4(f2t(v.x), f2t(v.y), f2t(v.z), f2t(v.w));
            *(uint4*)(Bs + bkr * GP + bnc + 4 * j) = u;
        }
        __syncthreads();

        #pragma unroll
        for (int ks = 0; ks < 4; ks++) {
            const int kk = ks * 8;
            unsigned a[2][4], b[8][2];
            #pragma unroll
            for (int mt = 0; mt < 2; mt++) {
                const int mb = m0w + mt * 16;
                a[mt][0] = As[(kk + tig) * GP + mb + g];
                a[mt][1] = As[(kk + tig) * GP + mb + g + 8];
                a[mt][2] = As[(kk + tig + 4) * GP + mb + g];
                a[mt][3] = As[(kk + tig + 4) * GP + mb + g + 8];
            }
            #pragma unroll
            for (int nt = 0; nt < 8; nt++) {
                b[nt][0] = Bs[(kk + tig) * GP + n0w + nt * 8 + g];
                b[nt][1] = Bs[(kk + tig + 4) * GP + n0w + nt * 8 + g];
            }
            #pragma unroll
            for (int mt = 0; mt < 2; mt++)
                #pragma unroll
                for (int nt = 0; nt < 8; nt++)
                    mma8(c[mt][nt], a[mt], b[nt]);
        }
        __syncthreads();
    }

    // epilogue: scatter to q/k/v
    #pragma unroll
    for (int mt = 0; mt < 2; mt++) {
        const int r0 = row0 + m0w + mt * 16 + g;
        const int r1 = r0 + 8;
        #pragma unroll
        for (int nt = 0; nt < 8; nt++) {
            const int n = col0 + n0w + nt * 8 + 2 * tig;
            qkv_store(r0, n,     c[mt][nt][0], bias);
            qkv_store(r0, n + 1, c[mt][nt][1], bias);
            qkv_store(r1, n,     c[mt][nt][2], bias);
            qkv_store(r1, n + 1, c[mt][nt][3], bias);
        }
    }
}

// =============================================================================
// Kernel 3: out projection via tf32 mma.sync — out = ctx @ Wo(1024x1024) + b
// =============================================================================
__global__ __launch_bounds__(256) void gemm_out_tc(
    const float* __restrict__ W,
    const float* __restrict__ bias,
    float* __restrict__ out)
{
    __shared__ unsigned As[32 * GP];
    __shared__ unsigned Bs[32 * GP];

    const int t    = threadIdx.x;
    const int w    = t >> 5, lane = t & 31;
    const int g    = lane >> 2, tig = lane & 3;
    const int row0 = blockIdx.y * 128;
    const int col0 = blockIdx.x * 128;
    const int m0w  = (w & 3) * 32;
    const int n0w  = (w >> 2) * 64;

    const int ar  = t & 127;
    const int ah  = (t >> 7) * 16;
    const int bkr = t >> 3;
    const int bnc = (t & 7) * 16;

    float c[2][8][4];
    #pragma unroll
    for (int mt = 0; mt < 2; mt++)
        #pragma unroll
        for (int nt = 0; nt < 8; nt++)
            #pragma unroll
            for (int j = 0; j < 4; j++) c[mt][nt][j] = 0.f;

    for (int k0 = 0; k0 < Dv; k0 += 32) {
        #pragma unroll
        for (int j = 0; j < 4; j++) {
            float4 v = *(const float4*)(g_ctx + (size_t)(row0 + ar) * Dv + k0 + ah + 4 * j);
            const int kb = ah + 4 * j;
            As[(kb + 0) * GP + ar] = f2t(v.x);
            As[(kb + 1) * GP + ar] = f2t(v.y);
            As[(kb + 2) * GP + ar] = f2t(v.z);
            As[(kb + 3) * GP + ar] = f2t(v.w);
        }
        #pragma unroll
        for (int j = 0; j < 4; j++) {
            float4 v = *(const float4*)(W + (size_t)(k0 + bkr) * Dv + col0 + bnc + 4 * j);
            uint4 u = make_uint4(f2t(v.x), f2t(v.y), f2t(v.z), f2t(v.w));
            *(uint4*)(Bs + bkr * GP + bnc + 4 * j) = u;
        }
        __syncthreads();

        #pragma unroll
        for (int ks = 0; ks < 4; ks++) {
            const int kk = ks * 8;
            unsigned a[2][4], b[8][2];
            #pragma unroll
            for (int mt = 0; mt < 2; mt++) {
                const int mb = m0w + mt * 16;
                a[mt][0] = As[(kk + tig) * GP + mb + g];
                a[mt][1] = As[(kk + tig) * GP + mb + g + 8];
                a[mt][2] = As[(kk + tig + 4) * GP + mb + g];
                a[mt][3] = As[(kk + tig + 4) * GP + mb + g + 8];
            }
            #pragma unroll
            for (int nt = 0; nt < 8; nt++) {
                b[nt][0] = Bs[(kk + tig) * GP + n0w + nt * 8 + g];
                b[nt][1] = Bs[(kk + tig + 4) * GP + n0w + nt * 8 + g];
            }
            #pragma unroll
            for (int mt = 0; mt < 2; mt++)
                #pragma unroll
                for (int nt = 0; nt < 8; nt++)
                    mma8(c[mt][nt], a[mt], b[nt]);
        }
        __syncthreads();
    }

    #pragma unroll
    for (int mt = 0; mt < 2; mt++) {
        const int r0 = row0 + m0w + mt * 16 + g;
        const int r1 = r0 + 8;
        #pragma unroll
        for (int nt = 0; nt < 8; nt++) {
            const int n = col0 + n0w + nt * 8 + 2 * tig;
            float2 v0 = make_float2(c[mt][nt][0] + bias[n], c[mt][nt][1] + bias[n + 1]);
            float2 v1 = make_float2(c[mt][nt][2] + bias[n], c[mt][nt][3] + bias[n + 1]);
            *(float2*)(out + (size_t)r0 * Dv + n) = v0;
            *(float2*)(out + (size_t)r1 * Dv + n) = v1;
        }
    }
}

// =============================================================================
// Kernel 2: tf32 tensor-core flash attention.
// Block = 128 threads (4 warps); each warp owns 16 q-rows x ALL 64 keys,
// so softmax is entirely register+shuffle resident. P (C-frag) -> A-frag via
// intra-quad shuffles. sK pitch 68 / sV pitch 72: conflict-free B-frag loads.
// =============================================================================
#define PK 68
#define PV 72

__global__ __launch_bounds__(128) void attn_tc(const int* __restrict__ mask)
{
    __shared__ unsigned sK[64 * PK];
    __shared__ unsigned sV[64 * PV];
    __shared__ int smask[64];

    const int t    = threadIdx.x;
    const int w    = t >> 5, lane = t & 31;
    const int g    = lane >> 2, tig = lane & 3;
    const int qt   = blockIdx.x;
    const int h    = blockIdx.y;
    const int b    = blockIdx.z;
    const size_t bh = ((size_t)b * Hv + h) * Sv;

    // ---- preload Q fragments (rows w*16 .. w*16+15), tf32 ----
    unsigned q[8][4];
    const float* qp = g_q + (bh + qt * 64 + w * 16) * HDv;
    #pragma unroll
    for (int ks = 0; ks < 8; ks++) {
        q[ks][0] = f2t(qp[g * 64       + ks * 8 + tig]);
        q[ks][1] = f2t(qp[(g + 8) * 64 + ks * 8 + tig]);
        q[ks][2] = f2t(qp[g * 64       + ks * 8 + tig + 4]);
        q[ks][3] = f2t(qp[(g + 8) * 64 + ks * 8 + tig + 4]);
    }

    float o[8][4];
    #pragma unroll
    for (int nt = 0; nt < 8; nt++)
        #pragma unroll
        for (int j = 0; j < 4; j++) o[nt][j] = 0.f;

    float m0r = -1e30f, m1r = -1e30f, l0 = 0.f, l1 = 0.f;

    const int lr = t >> 1;            // 0..63 tile-load row
    const int lh = (t & 1) * 32;      // col half
    const int sub = tig & 1;
    const int sl0 = (lane & ~3) | (tig >> 1);
    const int sl2 = sl0 + 2;

    for (int kt = 0; kt < Sv / 64; kt++) {
        __syncthreads();   // protect prior-iteration smem reads

        // ---- load K/V tiles as tf32 ----
        const float* kp = g_k + (bh + kt * 64) * HDv;
        const float* vp = g_v + (bh + kt * 64) * HDv;
        #pragma unroll
        for (int j = 0; j < 8; j++) {
            float4 kv = *(const float4*)(kp + lr * 64 + lh + 4 * j);
            *(uint4*)(sK + lr * PK + lh + 4 * j) =
                make_uint4(f2t(kv.x), f2t(kv.y), f2t(kv.z), f2t(kv.w));
            float4 vv = *(const float4*)(vp + lr * 64 + lh + 4 * j);
            *(uint4*)(sV + lr * PV + lh + 4 * j) =
                make_uint4(f2t(vv.x), f2t(vv.y), f2t(vv.z), f2t(vv.w));
        }
        if (t < 64) smask[t] = mask[b * Sv + kt * 64 + t];
        __syncthreads();

        // ---- S = Q K^T ----
        float s[8][4];
        #pragma unroll
        for (int nt = 0; nt < 8; nt++)
            #pragma unroll
            for (int j = 0; j < 4; j++) s[nt][j] = 0.f;

        #pragma unroll
        for (int ks = 0; ks < 8; ks++) {
            const int kk = ks * 8;
            #pragma unroll
            for (int nt = 0; nt < 8; nt++) {
                unsigned bb[2];
                bb[0] = sK[(nt * 8 + g) * PK + kk + tig];
                bb[1] = sK[(nt * 8 + g) * PK + kk + tig + 4];
                mma8(s[nt], q[ks], bb);
            }
        }

        // ---- mask ----
        #pragma unroll
        for (int nt = 0; nt < 8; nt++) {
            const int cc = nt * 8 + 2 * tig;
            if (!smask[cc])     { s[nt][0] = -1e30f; s[nt][2] = -1e30f; }
            if (!smask[cc + 1]) { s[nt][1] = -1e30f; s[nt][3] = -1e30f; }
        }

        // ---- row max (regs + quad shuffle) ----
        float mx0 = -1e30f, mx1 = -1e30f;
        #pragma unroll
        for (int nt = 0; nt < 8; nt++) {
            mx0 = fmaxf(mx0, fmaxf(s[nt][0], s[nt][1]));
            mx1 = fmaxf(mx1, fmaxf(s[nt][2], s[nt][3]));
        }
        mx0 = fmaxf(mx0, __shfl_xor_sync(0xffffffffu, mx0, 1));
        mx0 = fmaxf(mx0, __shfl_xor_sync(0xffffffffu, mx0, 2));
        mx1 = fmaxf(mx1, __shfl_xor_sync(0xffffffffu, mx1, 1));
        mx1 = fmaxf(mx1, __shfl_xor_sync(0xffffffffu, mx1, 2));

        const float mn0 = fmaxf(m0r, mx0);
        const float mn1 = fmaxf(m1r, mx1);
        const float cr0 = __expf(m0r - mn0);
        const float cr1 = __expf(m1r - mn1);
        m0r = mn0; m1r = mn1;

        // ---- exp + row sums ----
        float a0 = 0.f, a1 = 0.f;
        #pragma unroll
        for (int nt = 0; nt < 8; nt++) {
            s[nt][0] = __expf(s[nt][0] - mn0);
            s[nt][1] = __expf(s[nt][1] - mn0);
            s[nt][2] = __expf(s[nt][2] - mn1);
            s[nt][3] = __expf(s[nt][3] - mn1);
            a0 += s[nt][0] + s[nt][1];
            a1 += s[nt][2] + s[nt][3];
        }
        a0 += __shfl_xor_sync(0xffffffffu, a0, 1);
        a0 += __shfl_xor_sync(0xffffffffu, a0, 2);
        a1 += __shfl_xor_sync(0xffffffffu, a1, 1);
        a1 += __shfl_xor_sync(0xffffffffu, a1, 2);
        l0 = l0 * cr0 + a0;
        l1 = l1 * cr1 + a1;

        // ---- rescale O ----
        #pragma unroll
        for (int nt = 0; nt < 8; nt++) {
            o[nt][0] *= cr0; o[nt][1] *= cr0;
            o[nt][2] *= cr1; o[nt][3] *= cr1;
        }

        // ---- P -> tf32 (in place) ----
        #pragma unroll
        for (int nt = 0; nt < 8; nt++)
            #pragma unroll
            for (int j = 0; j < 4; j++)
                s[nt][j] = __uint_as_float(f2t(s[nt][j]));

        // ---- O += P V  (C-frag -> A-frag via quad shuffles) ----
        #pragma unroll
        for (int ks = 0; ks < 8; ks++) {
            unsigned a[4];
            float p0 = __shfl_sync(0xffffffffu, s[ks][0], sl0);
            float p1 = __shfl_sync(0xffffffffu, s[ks][1], sl0);
            a[0] = __float_as_uint(sub ? p1 : p0);
            float p2 = __shfl_sync(0xffffffffu, s[ks][2], sl0);
            float p3 = __shfl_sync(0xffffffffu, s[ks][3], sl0);
            a[1] = __float_as_uint(sub ? p3 : p2);
            float r0 = __shfl_sync(0xffffffffu, s[ks][0], sl2);
            float r1 = __shfl_sync(0xffffffffu, s[ks][1], sl2);
            a[2] = __float_as_uint(sub ? r1 : r0);
            float r2 = __shfl_sync(0xffffffffu, s[ks][2], sl2);
            float r3 = __shfl_sync(0xffffffffu, s[ks][3], sl2);
            a[3] = __float_as_uint(sub ? r3 : r2);

            const int kk = ks * 8;
            #pragma unroll
            for (int nt = 0; nt < 8; nt++) {
                unsigned bb[2];
                bb[0] = sV[(kk + tig) * PV + nt * 8 + g];
                bb[1] = sV[(kk + tig + 4) * PV + nt * 8 + g];
                mma8(o[nt], a, bb);
            }
        }
    }

    // ---- normalize and write context (b, s, d) ----
    const float inv0 = 1.0f / l0;
    const float inv1 = 1.0f / l1;
    float* op = g_ctx + (size_t)(b * Sv + qt * 64 + w * 16) * Dv + h * HDv;
    #pragma unroll
    for (int nt = 0; nt < 8; nt++) {
        const int cc = nt * 8 + 2 * tig;
        *(float2*)(op + (size_t)g * Dv + cc) =
            make_float2(o[nt][0] * inv0, o[nt][1] * inv0);
        *(float2*)(op + (size_t)(g + 8) * Dv + cc) =
            make_float2(o[nt][2] * inv1, o[nt][3] * inv1);
    }
}

// =============================================================================
extern "C" void kernel_launch(void* const* d_in, const int* in_sizes, int n_in,
                              void* d_out, int out_size)
{
    const float* x     = (const float*)d_in[0];
    const float* w_in  = (const float*)d_in[1];
    const float* b_in  = (const float*)d_in[2];
    const float* w_out = (const float*)d_in[3];
    const float* b_out = (const float*)d_in[4];
    const int*   mask  = (const int*)d_in[5];
    float* out = (float*)d_out;

    gemm_qkv_tc<<<dim3(N3v / 128, Mv / 128), 256>>>(x, w_in, b_in);
    attn_tc<<<dim3(Sv / 64, Hv, Bv), 128>>>(mask);
    gemm_out_tc<<<dim3(Dv / 128, Mv / 128), 256>>>(w_out, b_out, out);
}

// round 5
// speedup vs baseline: 2.3896x; 1.0007x over previous
#include <cuda_runtime.h>

// Problem constants
#define Bv 4
#define Sv 2048
#define Dv 1024
#define Hv 16
#define HDv 64
#define N3v 3072
#define Mv (Bv*Sv)   // 8192

// ---------------- scratch (device globals; no runtime allocation) -------------
__device__ __align__(256) float g_q[Bv*Hv*Sv*HDv];   // (b,h,s,hd), q pre-scaled
__device__ __align__(256) float g_k[Bv*Hv*Sv*HDv];
__device__ __align__(256) float g_v[Bv*Hv*Sv*HDv];
__device__ __align__(256) float g_ctx[(size_t)Mv*Dv]; // attention output (b,s,d)

// ---------------- tf32 helpers ------------------------------------------------
__device__ __forceinline__ unsigned f2t(float f) {
    unsigned u;
    asm("cvt.rna.tf32.f32 %0, %1;" : "=r"(u) : "f"(f));
    return u;
}

__device__ __forceinline__ void mma8(float* c, const unsigned* a, const unsigned* b) {
    asm volatile(
        "mma.sync.aligned.m16n8k8.row.col.f32.tf32.tf32.f32 "
        "{%0,%1,%2,%3},{%4,%5,%6,%7},{%8,%9},{%0,%1,%2,%3};\n"
        : "+f"(c[0]), "+f"(c[1]), "+f"(c[2]), "+f"(c[3])
        : "r"(a[0]), "r"(a[1]), "r"(a[2]), "r"(a[3]),
          "r"(b[0]), "r"(b[1]));
}

// =============================================================================
// QKV scatter epilogue helper
// =============================================================================
__device__ __forceinline__ void qkv_store(int m, int n, float v, const float* __restrict__ bias) {
    v += bias[n];
    const int bb  = m >> 11;
    const int s   = m & 2047;
    const int sel = n >> 10;      // 0=q 1=k 2=v
    const int d   = n & 1023;
    const int h   = d >> 6;
    const int hd  = d & 63;
    const int idx = ((bb * Hv + h) * Sv + s) * HDv + hd;
    if (sel == 0)      g_q[idx] = v * 0.125f;
    else if (sel == 1) g_k[idx] = v;
    else               g_v[idx] = v;
}

// =============================================================================
// Kernel 1: QKV projection via tf32 mma.sync — C = X(8192x1024) @ W(1024x3072)+b
// 128x128 tile, BK=32, 256 threads (8 warps), warp tile 32x64.
// smem pitch 136: fragment loads bank = 8*t4 + g (+const) -> conflict-free.
// =============================================================================
#define GP 136

__global__ __launch_bounds__(256) void gemm_qkv_tc(
    const float* __restrict__ X,
    const float* __restrict__ W,
    const float* __restrict__ bias)
{
    __shared__ unsigned As[32 * GP];
    __shared__ unsigned Bs[32 * GP];

    const int t    = threadIdx.x;
    const int w    = t >> 5, lane = t & 31;
    const int g    = lane >> 2, tig = lane & 3;
    const int row0 = blockIdx.y * 128;
    const int col0 = blockIdx.x * 128;
    const int m0w  = (w & 3) * 32;
    const int n0w  = (w >> 2) * 64;

    const int ar  = t & 127;          // A row
    const int ah  = (t >> 7) * 16;    // A k-half
    const int bkr = t >> 3;           // B k-row
    const int bnc = (t & 7) * 16;     // B n-chunk

    float c[2][8][4];
    #pragma unroll
    for (int mt = 0; mt < 2; mt++)
        #pragma unroll
        for (int nt = 0; nt < 8; nt++)
            #pragma unroll
            for (int j = 0; j < 4; j++) c[mt][nt][j] = 0.f;

    for (int k0 = 0; k0 < Dv; k0 += 32) {
        // A tile -> As[k][m] (transposed, tf32)
        #pragma unroll
        for (int j = 0; j < 4; j++) {
            float4 v = *(const float4*)(X + (size_t)(row0 + ar) * Dv + k0 + ah + 4 * j);
            const int kb = ah + 4 * j;
            As[(kb + 0) * GP + ar] = f2t(v.x);
            As[(kb + 1) * GP + ar] = f2t(v.y);
            As[(kb + 2) * GP + ar] = f2t(v.z);
            As[(kb + 3) * GP + ar] = f2t(v.w);
        }
        // B tile -> Bs[k][n] (tf32)
        #pragma unroll
        for (int j = 0; j < 4; j++) {
            float4 v = *(const float4*)(W + (size_t)(k0 + bkr) * N3v + col0 + bnc + 4 * j);
            uint4 u = make_uint4(f2t(v.x), f2t(v.y), f2t(v.z), f2t(v.w));
            *(uint4*)(Bs + bkr * GP + bnc + 4 * j) = u;
        }
        __syncthreads();

        #pragma unroll
        for (int ks = 0; ks < 4; ks++) {
            const int kk = ks * 8;
            unsigned a[2][4], b[8][2];
            #pragma unroll
            for (int mt = 0; mt < 2; mt++) {
                const int mb = m0w + mt * 16;
                a[mt][0] = As[(kk + tig) * GP + mb + g];
                a[mt][1] = As[(kk + tig) * GP + mb + g + 8];
                a[mt][2] = As[(kk + tig + 4) * GP + mb + g];
                a[mt][3] = As[(kk + tig + 4) * GP + mb + g + 8];
            }
            #pragma unroll
            for (int nt = 0; nt < 8; nt++) {
                b[nt][0] = Bs[(kk + tig) * GP + n0w + nt * 8 + g];
                b[nt][1] = Bs[(kk + tig + 4) * GP + n0w + nt * 8 + g];
            }
            #pragma unroll
            for (int mt = 0; mt < 2; mt++)
                #pragma unroll
                for (int nt = 0; nt < 8; nt++)
                    mma8(c[mt][nt], a[mt], b[nt]);
        }
        __syncthreads();
    }

    // epilogue: scatter to q/k/v
    #pragma unroll
    for (int mt = 0; mt < 2; mt++) {
        const int r0 = row0 + m0w + mt * 16 + g;
        const int r1 = r0 + 8;
        #pragma unroll
        for (int nt = 0; nt < 8; nt++) {
            const int n = col0 + n0w + nt * 8 + 2 * tig;
            qkv_store(r0, n,     c[mt][nt][0], bias);
            qkv_store(r0, n + 1, c[mt][nt][1], bias);
            qkv_store(r1, n,     c[mt][nt][2], bias);
            qkv_store(r1, n + 1, c[mt][nt][3], bias);
        }
    }
}

// =============================================================================
// Kernel 3: out projection via tf32 mma.sync — out = ctx @ Wo(1024x1024) + b
// =============================================================================
__global__ __launch_bounds__(256) void gemm_out_tc(
    const float* __restrict__ W,
    const float* __restrict__ bias,
    float* __restrict__ out)
{
    __shared__ unsigned As[32 * GP];
    __shared__ unsigned Bs[32 * GP];

    const int t    = threadIdx.x;
    const int w    = t >> 5, lane = t & 31;
    const int g    = lane >> 2, tig = lane & 3;
    const int row0 = blockIdx.y * 128;
    const int col0 = blockIdx.x * 128;
    const int m0w  = (w & 3) * 32;
    const int n0w  = (w >> 2) * 64;

    const int ar  = t & 127;
    const int ah  = (t >> 7) * 16;
    const int bkr = t >> 3;
    const int bnc = (t & 7) * 16;

    float c[2][8][4];
    #pragma unroll
    for (int mt = 0; mt < 2; mt++)
        #pragma unroll
        for (int nt = 0; nt < 8; nt++)
            #pragma unroll
            for (int j = 0; j < 4; j++) c[mt][nt][j] = 0.f;

    for (int k0 = 0; k0 < Dv; k0 += 32) {
        #pragma unroll
        for (int j = 0; j < 4; j++) {
            float4 v = *(const float4*)(g_ctx + (size_t)(row0 + ar) * Dv + k0 + ah + 4 * j);
            const int kb = ah + 4 * j;
            As[(kb + 0) * GP + ar] = f2t(v.x);
            As[(kb + 1) * GP + ar] = f2t(v.y);
            As[(kb + 2) * GP + ar] = f2t(v.z);
            As[(kb + 3) * GP + ar] = f2t(v.w);
        }
        #pragma unroll
        for (int j = 0; j < 4; j++) {
            float4 v = *(const float4*)(W + (size_t)(k0 + bkr) * Dv + col0 + bnc + 4 * j);
            uint4 u = make_uint4(f2t(v.x), f2t(v.y), f2t(v.z), f2t(v.w));
            *(uint4*)(Bs + bkr * GP + bnc + 4 * j) = u;
        }
        __syncthreads();

        #pragma unroll
        for (int ks = 0; ks < 4; ks++) {
            const int kk = ks * 8;
            unsigned a[2][4], b[8][2];
            #pragma unroll
            for (int mt = 0; mt < 2; mt++) {
                const int mb = m0w + mt * 16;
                a[mt][0] = As[(kk + tig) * GP + mb + g];
                a[mt][1] = As[(kk + tig) * GP + mb + g + 8];
                a[mt][2] = As[(kk + tig + 4) * GP + mb + g];
                a[mt][3] = As[(kk + tig + 4) * GP + mb + g + 8];
            }
            #pragma unroll
            for (int nt = 0; nt < 8; nt++) {
                b[nt][0] = Bs[(kk + tig) * GP + n0w + nt * 8 + g];
                b[nt][1] = Bs[(kk + tig + 4) * GP + n0w + nt * 8 + g];
            }
            #pragma unroll
            for (int mt = 0; mt < 2; mt++)
                #pragma unroll
                for (int nt = 0; nt < 8; nt++)
                    mma8(c[mt][nt], a[mt], b[nt]);
        }
        __syncthreads();
    }

    #pragma unroll
    for (int mt = 0; mt < 2; mt++) {
        const int r0 = row0 + m0w + mt * 16 + g;
        const int r1 = r0 + 8;
        #pragma unroll
        for (int nt = 0; nt < 8; nt++) {
            const int n = col0 + n0w + nt * 8 + 2 * tig;
            float2 v0 = make_float2(c[mt][nt][0] + bias[n], c[mt][nt][1] + bias[n + 1]);
            float2 v1 = make_float2(c[mt][nt][2] + bias[n], c[mt][nt][3] + bias[n + 1]);
            *(float2*)(out + (size_t)r0 * Dv + n) = v0;
            *(float2*)(out + (size_t)r1 * Dv + n) = v1;
        }
    }
}

// =============================================================================
// Kernel 2: tf32 tensor-core flash attention.
// Block = 128 threads (4 warps); each warp owns 16 q-rows x ALL 64 keys,
// so softmax is entirely register+shuffle resident. P (C-frag) -> A-frag via
// intra-quad shuffles. sK pitch 68 / sV pitch 72: conflict-free B-frag loads.
// =============================================================================
#define PK 68
#define PV 72

__global__ __launch_bounds__(128) void attn_tc(const int* __restrict__ mask)
{
    __shared__ unsigned sK[64 * PK];
    __shared__ unsigned sV[64 * PV];
    __shared__ int smask[64];

    const int t    = threadIdx.x;
    const int w    = t >> 5, lane = t & 31;
    const int g    = lane >> 2, tig = lane & 3;
    const int qt   = blockIdx.x;
    const int h    = blockIdx.y;
    const int b    = blockIdx.z;
    const size_t bh = ((size_t)b * Hv + h) * Sv;

    // ---- preload Q fragments (rows w*16 .. w*16+15), tf32 ----
    unsigned q[8][4];
    const float* qp = g_q + (bh + qt * 64 + w * 16) * HDv;
    #pragma unroll
    for (int ks = 0; ks < 8; ks++) {
        q[ks][0] = f2t(qp[g * 64       + ks * 8 + tig]);
        q[ks][1] = f2t(qp[(g + 8) * 64 + ks * 8 + tig]);
        q[ks][2] = f2t(qp[g * 64       + ks * 8 + tig + 4]);
        q[ks][3] = f2t(qp[(g + 8) * 64 + ks * 8 + tig + 4]);
    }

    float o[8][4];
    #pragma unroll
    for (int nt = 0; nt < 8; nt++)
        #pragma unroll
        for (int j = 0; j < 4; j++) o[nt][j] = 0.f;

    float m0r = -1e30f, m1r = -1e30f, l0 = 0.f, l1 = 0.f;

    const int lr = t >> 1;            // 0..63 tile-load row
    const int lh = (t & 1) * 32;      // col half
    const int sub = tig & 1;
    const int sl0 = (lane & ~3) | (tig >> 1);
    const int sl2 = sl0 + 2;

    for (int kt = 0; kt < Sv / 64; kt++) {
        __syncthreads();   // protect prior-iteration smem reads

        // ---- load K/V tiles as tf32 ----
        const float* kp = g_k + (bh + kt * 64) * HDv;
        const float* vp = g_v + (bh + kt * 64) * HDv;
        #pragma unroll
        for (int j = 0; j < 8; j++) {
            float4 kv = *(const float4*)(kp + lr * 64 + lh + 4 * j);
            *(uint4*)(sK + lr * PK + lh + 4 * j) =
                make_uint4(f2t(kv.x), f2t(kv.y), f2t(kv.z), f2t(kv.w));
            float4 vv = *(const float4*)(vp + lr * 64 + lh + 4 * j);
            *(uint4*)(sV + lr * PV + lh + 4 * j) =
                make_uint4(f2t(vv.x), f2t(vv.y), f2t(vv.z), f2t(vv.w));
        }
        if (t < 64) smask[t] = mask[b * Sv + kt * 64 + t];
        __syncthreads();

        // ---- S = Q K^T ----
        float s[8][4];
        #pragma unroll
        for (int nt = 0; nt < 8; nt++)
            #pragma unroll
            for (int j = 0; j < 4; j++) s[nt][j] = 0.f;

        #pragma unroll
        for (int ks = 0; ks < 8; ks++) {
            const int kk = ks * 8;
            #pragma unroll
            for (int nt = 0; nt < 8; nt++) {
                unsigned bb[2];
                bb[0] = sK[(nt * 8 + g) * PK + kk + tig];
                bb[1] = sK[(nt * 8 + g) * PK + kk + tig + 4];
                mma8(s[nt], q[ks], bb);
            }
        }

        // ---- mask ----
        #pragma unroll
        for (int nt = 0; nt < 8; nt++) {
            const int cc = nt * 8 + 2 * tig;
            if (!smask[cc])     { s[nt][0] = -1e30f; s[nt][2] = -1e30f; }
            if (!smask[cc + 1]) { s[nt][1] = -1e30f; s[nt][3] = -1e30f; }
        }

        // ---- row max (regs + quad shuffle) ----
        float mx0 = -1e30f, mx1 = -1e30f;
        #pragma unroll
        for (int nt = 0; nt < 8; nt++) {
            mx0 = fmaxf(mx0, fmaxf(s[nt][0], s[nt][1]));
            mx1 = fmaxf(mx1, fmaxf(s[nt][2], s[nt][3]));
        }
        mx0 = fmaxf(mx0, __shfl_xor_sync(0xffffffffu, mx0, 1));
        mx0 = fmaxf(mx0, __shfl_xor_sync(0xffffffffu, mx0, 2));
        mx1 = fmaxf(mx1, __shfl_xor_sync(0xffffffffu, mx1, 1));
        mx1 = fmaxf(mx1, __shfl_xor_sync(0xffffffffu, mx1, 2));

        const float mn0 = fmaxf(m0r, mx0);
        const float mn1 = fmaxf(m1r, mx1);
        const float cr0 = __expf(m0r - mn0);
        const float cr1 = __expf(m1r - mn1);
        m0r = mn0; m1r = mn1;

        // ---- exp + row sums ----
        float a0 = 0.f, a1 = 0.f;
        #pragma unroll
        for (int nt = 0; nt < 8; nt++) {
            s[nt][0] = __expf(s[nt][0] - mn0);
            s[nt][1] = __expf(s[nt][1] - mn0);
            s[nt][2] = __expf(s[nt][2] - mn1);
            s[nt][3] = __expf(s[nt][3] - mn1);
            a0 += s[nt][0] + s[nt][1];
            a1 += s[nt][2] + s[nt][3];
        }
        a0 += __shfl_xor_sync(0xffffffffu, a0, 1);
        a0 += __shfl_xor_sync(0xffffffffu, a0, 2);
        a1 += __shfl_xor_sync(0xffffffffu, a1, 1);
        a1 += __shfl_xor_sync(0xffffffffu, a1, 2);
        l0 = l0 * cr0 + a0;
        l1 = l1 * cr1 + a1;

        // ---- rescale O ----
        #pragma unroll
        for (int nt = 0; nt < 8; nt++) {
            o[nt][0] *= cr0; o[nt][1] *= cr0;
            o[nt][2] *= cr1; o[nt][3] *= cr1;
        }

        // ---- P -> tf32 (in place) ----
        #pragma unroll
        for (int nt = 0; nt < 8; nt++)
            #pragma unroll
            for (int j = 0; j < 4; j++)
                s[nt][j] = __uint_as_float(f2t(s[nt][j]));

        // ---- O += P V  (C-frag -> A-frag via quad shuffles) ----
        #pragma unroll
        for (int ks = 0; ks < 8; ks++) {
            unsigned a[4];
            float p0 = __shfl_sync(0xffffffffu, s[ks][0], sl0);
            float p1 = __shfl_sync(0xffffffffu, s[ks][1], sl0);
            a[0] = __float_as_uint(sub ? p1 : p0);
            float p2 = __shfl_sync(0xffffffffu, s[ks][2], sl0);
            float p3 = __shfl_sync(0xffffffffu, s[ks][3], sl0);
            a[1] = __float_as_uint(sub ? p3 : p2);
            float r0 = __shfl_sync(0xffffffffu, s[ks][0], sl2);
            float r1 = __shfl_sync(0xffffffffu, s[ks][1], sl2);
            a[2] = __float_as_uint(sub ? r1 : r0);
            float r2 = __shfl_sync(0xffffffffu, s[ks][2], sl2);
            float r3 = __shfl_sync(0xffffffffu, s[ks][3], sl2);
            a[3] = __float_as_uint(sub ? r3 : r2);

            const int kk = ks * 8;
            #pragma unroll
            for (int nt = 0; nt < 8; nt++) {
                unsigned bb[2];
                bb[0] = sV[(kk + tig) * PV + nt * 8 + g];
                bb[1] = sV[(kk + tig + 4) * PV + nt * 8 + g];
                mma8(o[nt], a, bb);
            }
        }
    }

    // ---- normalize and write context (b, s, d) ----
    const float inv0 = 1.0f / l0;
    const float inv1 = 1.0f / l1;
    float* op = g_ctx + (size_t)(b * Sv + qt * 64 + w * 16) * Dv + h * HDv;
    #pragma unroll
    for (int nt = 0; nt < 8; nt++) {
        const int cc = nt * 8 + 2 * tig;
        *(float2*)(op + (size_t)g * Dv + cc) =
            make_float2(o[nt][0] * inv0, o[nt][1] * inv0);
        *(float2*)(op + (size_t)(g + 8) * Dv + cc) =
            make_float2(o[nt][2] * inv1, o[nt][3] * inv1);
    }
}

// =============================================================================
extern "C" void kernel_launch(void* const* d_in, const int* in_sizes, int n_in,
                              void* d_out, int out_size)
{
    const float* x     = (const float*)d_in[0];
    const float* w_in  = (const float*)d_in[1];
    const float* b_in  = (const float*)d_in[2];
    const float* w_out = (const float*)d_in[3];
    const float* b_out = (const float*)d_in[4];
    const int*   mask  = (const int*)d_in[5];
    float* out = (float*)d_out;

    gemm_qkv_tc<<<dim3(N3v / 128, Mv / 128), 256>>>(x, w_in, b_in);
    attn_tc<<<dim3(Sv / 64, Hv, Bv), 128>>>(mask);
    gemm_out_tc<<<dim3(Dv / 128, Mv / 128), 256>>>(w_out, b_out, out);
}